// round 11
// baseline (speedup 1.0000x reference)
#include <cuda_runtime.h>
#include <cuda_bf16.h>
#include <cstdint>

// Problem shape (fixed by setup_inputs)
static const int NB = 2, NC = 512, NN = 4096, NG = 32, CPG = 16;

// ---------------- scratch (allocation-free: __device__ globals) -------------
__device__ __align__(256) __nv_bfloat16 g_tT[(size_t)NB * NN * NC]; // gn(x)^T [b][n][c]
__device__ __align__(256) __nv_bfloat16 g_q [(size_t)NB * NN * NC]; // q  [b][n][o]
__device__ __align__(256) __nv_bfloat16 g_k [(size_t)NB * NN * NC]; // k  [b][n][o]
__device__ __align__(256) __nv_bfloat16 g_v [(size_t)NB * NC * NN]; // v  [b][o][m]
__device__ __align__(256) __nv_bfloat16 g_s [(size_t)NB * NN * NN]; // scores/attn [b][n][m]
__device__ __align__(256) __nv_bfloat16 g_ao[(size_t)NB * NN * NC]; // attn@v [b][n][c]
__device__ __align__(256) __nv_bfloat16 g_wb[4 * 512 * 512];        // wq,wk,wv,wp in bf16

__device__ __forceinline__ uint32_t smem_u32(const void* p) {
    uint32_t a;
    asm("{ .reg .u64 t; cvta.to.shared.u64 t, %1; cvt.u32.u64 %0, t; }"
        : "=r"(a) : "l"(p));
    return a;
}

// ---------------- weight fp32 -> bf16 ---------------------------------------
__global__ void convw_kernel(const float* __restrict__ w0, const float* __restrict__ w1,
                             const float* __restrict__ w2, const float* __restrict__ w3,
                             __nv_bfloat16* __restrict__ out) {
    int idx = blockIdx.x * 256 + threadIdx.x;           // 4*262144 total
    const float* src = (idx < 262144) ? w0 : (idx < 524288) ? w1
                     : (idx < 786432) ? w2 : w3;
    out[idx] = __float2bfloat16(src[idx & 262143]);
}

// ---------------- GroupNorm -> transposed bf16 [b][n][c] ---------------------
__global__ void groupnorm_kernel(const float* __restrict__ x,
                                 const float* __restrict__ scale,
                                 const float* __restrict__ bias,
                                 __nv_bfloat16* __restrict__ tT) {
    const int chunk = CPG * NN;                 // 65536
    const int bidx = blockIdx.x;
    const int b = bidx / NG, g = bidx % NG;
    const size_t base = (size_t)bidx * chunk;
    const int tid = threadIdx.x;

    float sum = 0.f, sumsq = 0.f;
    for (int i = tid; i < chunk; i += 256) {
        float v = x[base + i];
        sum += v; sumsq += v * v;
    }
    __shared__ float ssum[256], ssq[256];
    ssum[tid] = sum; ssq[tid] = sumsq;
    __syncthreads();
    for (int s = 128; s > 0; s >>= 1) {
        if (tid < s) { ssum[tid] += ssum[tid + s]; ssq[tid] += ssq[tid + s]; }
        __syncthreads();
    }
    const float mean = ssum[0] / (float)chunk;
    const float var  = ssq[0] / (float)chunk - mean * mean;
    const float inv  = rsqrtf(var + 1e-6f);

    const int ch0 = g * CPG;
    const int csub = (tid & 3) * 4;             // channel quad within group
    float sc[4], bi[4];
    #pragma unroll
    for (int j = 0; j < 4; j++) {
        sc[j] = scale[ch0 + csub + j] * inv;
        bi[j] = bias[ch0 + csub + j] - mean * sc[j];
    }
    for (int n = (tid >> 2); n < NN; n += 64) {
        float o0 = x[base + (size_t)(csub + 0) * NN + n] * sc[0] + bi[0];
        float o1 = x[base + (size_t)(csub + 1) * NN + n] * sc[1] + bi[1];
        float o2 = x[base + (size_t)(csub + 2) * NN + n] * sc[2] + bi[2];
        float o3 = x[base + (size_t)(csub + 3) * NN + n] * sc[3] + bi[3];
        __nv_bfloat162 p0 = __floats2bfloat162_rn(o0, o1);
        __nv_bfloat162 p1 = __floats2bfloat162_rn(o2, o3);
        uint2 u = make_uint2(*(uint32_t*)&p0, *(uint32_t*)&p1);
        *(uint2*)&tT[((size_t)b * NN + n) * NC + ch0 + csub] = u;
    }
}

// ---------------- mma.sync bf16 GEMM -----------------------------------------
// D[m][n] = alpha * sum_k A[m][k]*B[n][k] (+bias)(+resid). A,B bf16 K-major.
// Block 64x128, 8 warps (2M x 4N), warp tile 32x32, K-tile 32 bf16, 4-stage cp.async.
// Small tile -> 32 acc regs/thread -> 3 CTAs/SM (24 warps) for latency hiding.
// OUTBF: 1 bf16 out, 0 fp32 out.  BIAS: 0 none, 1 row (bias[m]), 2 col (bias[n]).
static const int STG_A = 5120;                 // 64 rows * 80B (64B data + 16 pad)
static const int STG_B = 10240;                // 128 rows * 80B
static const int SMEM_BYTES = 4 * (STG_A + STG_B);   // 61440

template <int OUTBF, int BIAS, int RESID>
__global__ void __launch_bounds__(256, 3)
mma_gemm(const __nv_bfloat16* __restrict__ Ag, const __nv_bfloat16* __restrict__ Bg,
         const float* __restrict__ bias, const float* __restrict__ Rg,
         void* __restrict__ Cg_, int M, int N, int K, float alpha,
         size_t sA, size_t sB, size_t sC) {
    extern __shared__ char smem[];
    const uint32_t sbase = smem_u32(smem);
    const uint32_t SAb = sbase, SBb = sbase + 4 * STG_A;

    Ag += (size_t)blockIdx.z * sA;
    Bg += (size_t)blockIdx.z * sB;

    const int tid = threadIdx.x, lane = tid & 31, wid = tid >> 5;
    const int mw = wid >> 2, nw = wid & 3;       // warp grid 2x4, warp tile 32x32
    const int rowBase = blockIdx.y * 64;
    const int colBase = blockIdx.x * 128;

    float acc[2][4][4];
    #pragma unroll
    for (int i = 0; i < 2; i++)
        #pragma unroll
        for (int j = 0; j < 4; j++)
            #pragma unroll
            for (int l = 0; l < 4; l++) acc[i][j][l] = 0.f;

    const int r_ld = tid >> 2, kb_ld = tid & 3;  // A: 1 chunk, B: 2 chunks per thread
    auto issue = [&](int st, int kt) {
        uint32_t sa0 = SAb + st * STG_A + r_ld * 80 + kb_ld * 16;
        const __nv_bfloat16* ga0 = Ag + (size_t)(rowBase + r_ld) * K + kt * 32 + kb_ld * 8;
        asm volatile("cp.async.cg.shared.global [%0], [%1], 16;" :: "r"(sa0), "l"(ga0));
        uint32_t sb0 = SBb + st * STG_B + r_ld * 80 + kb_ld * 16;
        const __nv_bfloat16* gb0 = Bg + (size_t)(colBase + r_ld) * K + kt * 32 + kb_ld * 8;
        asm volatile("cp.async.cg.shared.global [%0], [%1], 16;" :: "r"(sb0), "l"(gb0));
        uint32_t sb1 = sb0 + 64 * 80;
        const __nv_bfloat16* gb1 = gb0 + (size_t)64 * K;
        asm volatile("cp.async.cg.shared.global [%0], [%1], 16;" :: "r"(sb1), "l"(gb1));
    };

    const int ntiles = K / 32;
    issue(0, 0); asm volatile("cp.async.commit_group;" ::: "memory");
    issue(1, 1); asm volatile("cp.async.commit_group;" ::: "memory");
    issue(2, 2); asm volatile("cp.async.commit_group;" ::: "memory");

    for (int kt = 0; kt < ntiles; kt++) {
        asm volatile("cp.async.wait_group 2;" ::: "memory");
        __syncthreads();
        const int lt = kt + 3;
        if (lt < ntiles) issue(lt & 3, lt);
        asm volatile("cp.async.commit_group;" ::: "memory");

        const uint32_t ab = SAb + (kt & 3) * STG_A;
        const uint32_t bb = SBb + (kt & 3) * STG_B;
        #pragma unroll
        for (int k16 = 0; k16 < 2; k16++) {
            uint32_t a[2][4], b[4][2];
            #pragma unroll
            for (int mf = 0; mf < 2; mf++) {
                uint32_t ad = ab + (uint32_t)(mw * 32 + mf * 16 + (lane & 15)) * 80
                            + k16 * 32 + ((lane >> 4) * 16);
                asm volatile("ldmatrix.sync.aligned.m8n8.x4.shared.b16 {%0,%1,%2,%3},[%4];"
                    : "=r"(a[mf][0]), "=r"(a[mf][1]), "=r"(a[mf][2]), "=r"(a[mf][3])
                    : "r"(ad));
            }
            #pragma unroll
            for (int b2 = 0; b2 < 2; b2++) {
                const int g = lane >> 3;
                uint32_t bd = bb + (uint32_t)(nw * 32 + b2 * 16 + (g >> 1) * 8 + (lane & 7)) * 80
                            + k16 * 32 + (g & 1) * 16;
                uint32_t r0, r1, r2, r3;
                asm volatile("ldmatrix.sync.aligned.m8n8.x4.shared.b16 {%0,%1,%2,%3},[%4];"
                    : "=r"(r0), "=r"(r1), "=r"(r2), "=r"(r3) : "r"(bd));
                b[b2 * 2][0] = r0; b[b2 * 2][1] = r1;
                b[b2 * 2 + 1][0] = r2; b[b2 * 2 + 1][1] = r3;
            }
            #pragma unroll
            for (int mf = 0; mf < 2; mf++)
                #pragma unroll
                for (int nf = 0; nf < 4; nf++)
                    asm volatile(
                        "mma.sync.aligned.m16n8k16.row.col.f32.bf16.bf16.f32 "
                        "{%0,%1,%2,%3},{%4,%5,%6,%7},{%8,%9},{%0,%1,%2,%3};"
                        : "+f"(acc[mf][nf][0]), "+f"(acc[mf][nf][1]),
                          "+f"(acc[mf][nf][2]), "+f"(acc[mf][nf][3])
                        : "r"(a[mf][0]), "r"(a[mf][1]), "r"(a[mf][2]), "r"(a[mf][3]),
                          "r"(b[nf][0]), "r"(b[nf][1]));
        }
    }

    // Epilogue
    float* Cf = (float*)Cg_ + (size_t)blockIdx.z * sC;
    __nv_bfloat16* Cb = (__nv_bfloat16*)Cg_ + (size_t)blockIdx.z * sC;
    const float* Rp = RESID ? (Rg + (size_t)blockIdx.z * sC) : nullptr;
    #pragma unroll
    for (int mf = 0; mf < 2; mf++) {
        const int r0 = rowBase + mw * 32 + mf * 16 + (lane >> 2);
        #pragma unroll
        for (int nf = 0; nf < 4; nf++) {
            const int col = colBase + nw * 32 + nf * 8 + (lane & 3) * 2;
            float v0 = acc[mf][nf][0] * alpha, v1 = acc[mf][nf][1] * alpha;
            float v2 = acc[mf][nf][2] * alpha, v3 = acc[mf][nf][3] * alpha;
            if (BIAS == 2) {
                float b0 = bias[col], b1 = bias[col + 1];
                v0 += b0; v1 += b1; v2 += b0; v3 += b1;
            }
            if (BIAS == 1) {
                v0 += bias[r0]; v1 += bias[r0];
                v2 += bias[r0 + 8]; v3 += bias[r0 + 8];
            }
            if (RESID) {
                v0 += Rp[(size_t)r0 * N + col];       v1 += Rp[(size_t)r0 * N + col + 1];
                v2 += Rp[(size_t)(r0 + 8) * N + col]; v3 += Rp[(size_t)(r0 + 8) * N + col + 1];
            }
            if (OUTBF) {
                __nv_bfloat162 p0 = __floats2bfloat162_rn(v0, v1);
                __nv_bfloat162 p1 = __floats2bfloat162_rn(v2, v3);
                *(__nv_bfloat162*)(Cb + (size_t)r0 * N + col) = p0;
                *(__nv_bfloat162*)(Cb + (size_t)(r0 + 8) * N + col) = p1;
            } else {
                *(float2*)(Cf + (size_t)r0 * N + col) = make_float2(v0, v1);
                *(float2*)(Cf + (size_t)(r0 + 8) * N + col) = make_float2(v2, v3);
            }
        }
    }
}

// ---------------- Row softmax (bf16 in/out, fp32 math) -----------------------
__global__ void softmax_kernel(__nv_bfloat16* __restrict__ s) {
    __nv_bfloat162* row = (__nv_bfloat162*)(s + (size_t)blockIdx.x * NN);
    const int tid = threadIdx.x;
    float2 vals[8];
    float m = -1e30f;
    #pragma unroll
    for (int i = 0; i < 8; i++) {
        __nv_bfloat162 p = row[tid + i * 256];
        vals[i].x = __low2float(p); vals[i].y = __high2float(p);
        m = fmaxf(m, fmaxf(vals[i].x, vals[i].y));
    }
    __shared__ float red[256];
    red[tid] = m; __syncthreads();
    for (int st = 128; st > 0; st >>= 1) {
        if (tid < st) red[tid] = fmaxf(red[tid], red[tid + st]);
        __syncthreads();
    }
    m = red[0];
    __syncthreads();
    float sum = 0.f;
    #pragma unroll
    for (int i = 0; i < 8; i++) {
        vals[i].x = __expf(vals[i].x - m);
        vals[i].y = __expf(vals[i].y - m);
        sum += vals[i].x + vals[i].y;
    }
    red[tid] = sum; __syncthreads();
    for (int st = 128; st > 0; st >>= 1) {
        if (tid < st) red[tid] += red[tid + st];
        __syncthreads();
    }
    const float inv = 1.f / red[0];
    #pragma unroll
    for (int i = 0; i < 8; i++)
        row[tid + i * 256] = __floats2bfloat162_rn(vals[i].x * inv, vals[i].y * inv);
}

// ---------------- launch -----------------------------------------------------
extern "C" void kernel_launch(void* const* d_in, const int* in_sizes, int n_in,
                              void* d_out, int out_size) {
    const float* x   = (const float*)d_in[0];
    const float* gns = (const float*)d_in[1];
    const float* gnb = (const float*)d_in[2];
    const float* wq  = (const float*)d_in[3];
    const float* bq  = (const float*)d_in[4];
    const float* wk  = (const float*)d_in[5];
    const float* bk  = (const float*)d_in[6];
    const float* wv  = (const float*)d_in[7];
    const float* bv  = (const float*)d_in[8];
    const float* wp  = (const float*)d_in[9];
    const float* bp  = (const float*)d_in[10];
    float* out = (float*)d_out;

    __nv_bfloat16 *tT, *q, *k, *v, *s, *ao, *wb;
    cudaGetSymbolAddress((void**)&tT, g_tT);
    cudaGetSymbolAddress((void**)&q,  g_q);
    cudaGetSymbolAddress((void**)&k,  g_k);
    cudaGetSymbolAddress((void**)&v,  g_v);
    cudaGetSymbolAddress((void**)&s,  g_s);
    cudaGetSymbolAddress((void**)&ao, g_ao);
    cudaGetSymbolAddress((void**)&wb, g_wb);
    __nv_bfloat16 *wqb = wb, *wkb = wb + 262144, *wvb = wb + 524288, *wpb = wb + 786432;

    cudaFuncSetAttribute(mma_gemm<1,2,0>, cudaFuncAttributeMaxDynamicSharedMemorySize, SMEM_BYTES);
    cudaFuncSetAttribute(mma_gemm<1,1,0>, cudaFuncAttributeMaxDynamicSharedMemorySize, SMEM_BYTES);
    cudaFuncSetAttribute(mma_gemm<1,0,0>, cudaFuncAttributeMaxDynamicSharedMemorySize, SMEM_BYTES);
    cudaFuncSetAttribute(mma_gemm<0,1,1>, cudaFuncAttributeMaxDynamicSharedMemorySize, SMEM_BYTES);

    const size_t S  = (size_t)NN * NC;   // per-batch stride for [n][c]-like tensors
    const size_t SS = (size_t)NN * NN;   // scores stride

    // 0) weights -> bf16
    convw_kernel<<<4096, 256>>>(wq, wk, wv, wp, wb);
    // 1) GroupNorm -> tT bf16 [b][n][c]
    groupnorm_kernel<<<NB * NG, 256>>>(x, gns, gnb, tT);

    // 2) q[n][o] = tT[n][:].wq[o][:] + bq[o]
    mma_gemm<1,2,0><<<dim3(NC/128, NN/64, NB), 256, SMEM_BYTES>>>(
        tT, wqb, bq, nullptr, q, NN, NC, NC, 1.f, S, 0, S);
    // 3) k[n][o]
    mma_gemm<1,2,0><<<dim3(NC/128, NN/64, NB), 256, SMEM_BYTES>>>(
        tT, wkb, bk, nullptr, k, NN, NC, NC, 1.f, S, 0, S);
    // 4) v[o][m] = wv[o][:].tT[m][:] + bv[o]  (row bias)
    mma_gemm<1,1,0><<<dim3(NN/128, NC/64, NB), 256, SMEM_BYTES>>>(
        wvb, tT, bv, nullptr, v, NC, NN, NC, 1.f, 0, S, S);
    // 5) scores[n][m] = alpha * q[n][:].k[m][:]
    mma_gemm<1,0,0><<<dim3(NN/128, NN/64, NB), 256, SMEM_BYTES>>>(
        q, k, nullptr, nullptr, s, NN, NN, NC, 0.044194173824159216f, S, S, SS);
    // 6) softmax rows (in-place bf16)
    softmax_kernel<<<NB * NN, 256>>>(s);
    // 7) ao[n][c] = attn[n][:].v[c][:]
    mma_gemm<1,0,0><<<dim3(NC/128, NN/64, NB), 256, SMEM_BYTES>>>(
        s, v, nullptr, nullptr, ao, NN, NC, NN, 1.f, SS, S, S);
    // 8) out[o][n] = wp[o][:].ao[n][:] + bp[o] + x[o][n]
    mma_gemm<0,1,1><<<dim3(NN/128, NC/64, NB), 256, SMEM_BYTES>>>(
        wpb, ao, bp, x, out, NC, NN, NC, 1.f, 0, S, S);
}

// round 14
// speedup vs baseline: 1.0957x; 1.0957x over previous
#include <cuda_runtime.h>
#include <cuda_bf16.h>
#include <cstdint>

// Problem shape (fixed by setup_inputs)
static const int NB = 2, NC = 512, NN = 4096, NG = 32, CPG = 16;

// ---------------- scratch (allocation-free: __device__ globals) -------------
__device__ __align__(256) __nv_bfloat16 g_tT[(size_t)NB * NN * NC]; // gn(x)^T [b][n][c]
__device__ __align__(256) __nv_bfloat16 g_q [(size_t)NB * NN * NC]; // q  [b][n][o]
__device__ __align__(256) __nv_bfloat16 g_k [(size_t)NB * NN * NC]; // k  [b][n][o]
__device__ __align__(256) __nv_bfloat16 g_v [(size_t)NB * NC * NN]; // v  [b][o][m]
__device__ __align__(256) __nv_bfloat16 g_s [(size_t)NB * NN * NN]; // scores/attn [b][n][m]
__device__ __align__(256) __nv_bfloat16 g_ao[(size_t)NB * NN * NC]; // attn@v [b][n][c]
__device__ __align__(256) __nv_bfloat16 g_wb[4 * 512 * 512];        // wq,wk,wv,wp in bf16

__device__ __forceinline__ uint32_t smem_u32(const void* p) {
    uint32_t a;
    asm("{ .reg .u64 t; cvta.to.shared.u64 t, %1; cvt.u32.u64 %0, t; }"
        : "=r"(a) : "l"(p));
    return a;
}

// ---------------- weight fp32 -> bf16 ---------------------------------------
__global__ void convw_kernel(const float* __restrict__ w0, const float* __restrict__ w1,
                             const float* __restrict__ w2, const float* __restrict__ w3,
                             __nv_bfloat16* __restrict__ out) {
    int idx = blockIdx.x * 256 + threadIdx.x;           // 4*262144 total
    const float* src = (idx < 262144) ? w0 : (idx < 524288) ? w1
                     : (idx < 786432) ? w2 : w3;
    out[idx] = __float2bfloat16(src[idx & 262143]);
}

// ---------------- GroupNorm -> transposed bf16 [b][n][c] ---------------------
__global__ void groupnorm_kernel(const float* __restrict__ x,
                                 const float* __restrict__ scale,
                                 const float* __restrict__ bias,
                                 __nv_bfloat16* __restrict__ tT) {
    const int chunk = CPG * NN;                 // 65536
    const int bidx = blockIdx.x;
    const int b = bidx / NG, g = bidx % NG;
    const size_t base = (size_t)bidx * chunk;
    const int tid = threadIdx.x;

    float sum = 0.f, sumsq = 0.f;
    for (int i = tid; i < chunk; i += 256) {
        float v = x[base + i];
        sum += v; sumsq += v * v;
    }
    __shared__ float ssum[256], ssq[256];
    ssum[tid] = sum; ssq[tid] = sumsq;
    __syncthreads();
    for (int s = 128; s > 0; s >>= 1) {
        if (tid < s) { ssum[tid] += ssum[tid + s]; ssq[tid] += ssq[tid + s]; }
        __syncthreads();
    }
    const float mean = ssum[0] / (float)chunk;
    const float var  = ssq[0] / (float)chunk - mean * mean;
    const float inv  = rsqrtf(var + 1e-6f);

    const int ch0 = g * CPG;
    const int csub = (tid & 3) * 4;             // channel quad within group
    float sc[4], bi[4];
    #pragma unroll
    for (int j = 0; j < 4; j++) {
        sc[j] = scale[ch0 + csub + j] * inv;
        bi[j] = bias[ch0 + csub + j] - mean * sc[j];
    }
    for (int n = (tid >> 2); n < NN; n += 64) {
        float o0 = x[base + (size_t)(csub + 0) * NN + n] * sc[0] + bi[0];
        float o1 = x[base + (size_t)(csub + 1) * NN + n] * sc[1] + bi[1];
        float o2 = x[base + (size_t)(csub + 2) * NN + n] * sc[2] + bi[2];
        float o3 = x[base + (size_t)(csub + 3) * NN + n] * sc[3] + bi[3];
        __nv_bfloat162 p0 = __floats2bfloat162_rn(o0, o1);
        __nv_bfloat162 p1 = __floats2bfloat162_rn(o2, o3);
        uint2 u = make_uint2(*(uint32_t*)&p0, *(uint32_t*)&p1);
        *(uint2*)&tT[((size_t)b * NN + n) * NC + ch0 + csub] = u;
    }
}

// ---------------- mma.sync bf16 GEMM -----------------------------------------
// D[m][n] = alpha * sum_k A[m][k]*B[n][k] (+bias)(+resid). A,B bf16 K-major.
// Block 128x128, 16 warps (4M x 4N), warp tile 32x32, K-tile 32, 4-stage cp.async.
// 512 thr/CTA, 32 acc regs -> <=64 regs -> 2 CTAs/SM = 32 warps resident.
// OUTBF: 1 bf16 out, 0 fp32 out.  BIAS: 0 none, 1 row (bias[m]), 2 col (bias[n]).
static const int STG = 10240;                 // 128 rows * 80B (64B data + 16 pad)
static const int SMEM_BYTES = 8 * STG;        // A 4 stages + B 4 stages = 80KB

template <int OUTBF, int BIAS, int RESID>
__global__ void __launch_bounds__(512, 2)
mma_gemm(const __nv_bfloat16* __restrict__ Ag, const __nv_bfloat16* __restrict__ Bg,
         const float* __restrict__ bias, const float* __restrict__ Rg,
         void* __restrict__ Cg_, int M, int N, int K, float alpha,
         size_t sA, size_t sB, size_t sC) {
    extern __shared__ char smem[];
    const uint32_t sbase = smem_u32(smem);
    const uint32_t SAb = sbase, SBb = sbase + 4 * STG;

    Ag += (size_t)blockIdx.z * sA;
    Bg += (size_t)blockIdx.z * sB;

    const int tid = threadIdx.x, lane = tid & 31, wid = tid >> 5;
    const int mw = wid >> 2, nw = wid & 3;       // warp grid 4x4, warp tile 32x32
    const int rowBase = blockIdx.y * 128;
    const int colBase = blockIdx.x * 128;

    float acc[2][4][4];
    #pragma unroll
    for (int i = 0; i < 2; i++)
        #pragma unroll
        for (int j = 0; j < 4; j++)
            #pragma unroll
            for (int l = 0; l < 4; l++) acc[i][j][l] = 0.f;

    const int r_ld = tid >> 2, kb_ld = tid & 3;  // 1 chunk per thread per operand
    auto issue = [&](int st, int kt) {
        uint32_t sa0 = SAb + st * STG + r_ld * 80 + kb_ld * 16;
        const __nv_bfloat16* ga0 = Ag + (size_t)(rowBase + r_ld) * K + kt * 32 + kb_ld * 8;
        asm volatile("cp.async.cg.shared.global [%0], [%1], 16;" :: "r"(sa0), "l"(ga0));
        uint32_t sb0 = SBb + st * STG + r_ld * 80 + kb_ld * 16;
        const __nv_bfloat16* gb0 = Bg + (size_t)(colBase + r_ld) * K + kt * 32 + kb_ld * 8;
        asm volatile("cp.async.cg.shared.global [%0], [%1], 16;" :: "r"(sb0), "l"(gb0));
    };

    const int ntiles = K / 32;
    issue(0, 0); asm volatile("cp.async.commit_group;" ::: "memory");
    issue(1, 1); asm volatile("cp.async.commit_group;" ::: "memory");
    issue(2, 2); asm volatile("cp.async.commit_group;" ::: "memory");

    for (int kt = 0; kt < ntiles; kt++) {
        asm volatile("cp.async.wait_group 2;" ::: "memory");
        __syncthreads();
        const int lt = kt + 3;
        if (lt < ntiles) issue(lt & 3, lt);
        asm volatile("cp.async.commit_group;" ::: "memory");

        const uint32_t ab = SAb + (kt & 3) * STG;
        const uint32_t bb = SBb + (kt & 3) * STG;
        #pragma unroll
        for (int k16 = 0; k16 < 2; k16++) {
            uint32_t a[2][4], b[4][2];
            #pragma unroll
            for (int mf = 0; mf < 2; mf++) {
                uint32_t ad = ab + (uint32_t)(mw * 32 + mf * 16 + (lane & 15)) * 80
                            + k16 * 32 + ((lane >> 4) * 16);
                asm volatile("ldmatrix.sync.aligned.m8n8.x4.shared.b16 {%0,%1,%2,%3},[%4];"
                    : "=r"(a[mf][0]), "=r"(a[mf][1]), "=r"(a[mf][2]), "=r"(a[mf][3])
                    : "r"(ad));
            }
            #pragma unroll
            for (int b2 = 0; b2 < 2; b2++) {
                const int g = lane >> 3;
                uint32_t bd = bb + (uint32_t)(nw * 32 + b2 * 16 + (g >> 1) * 8 + (lane & 7)) * 80
                            + k16 * 32 + (g & 1) * 16;
                uint32_t r0, r1, r2, r3;
                asm volatile("ldmatrix.sync.aligned.m8n8.x4.shared.b16 {%0,%1,%2,%3},[%4];"
                    : "=r"(r0), "=r"(r1), "=r"(r2), "=r"(r3) : "r"(bd));
                b[b2 * 2][0] = r0; b[b2 * 2][1] = r1;
                b[b2 * 2 + 1][0] = r2; b[b2 * 2 + 1][1] = r3;
            }
            #pragma unroll
            for (int mf = 0; mf < 2; mf++)
                #pragma unroll
                for (int nf = 0; nf < 4; nf++)
                    asm volatile(
                        "mma.sync.aligned.m16n8k16.row.col.f32.bf16.bf16.f32 "
                        "{%0,%1,%2,%3},{%4,%5,%6,%7},{%8,%9},{%0,%1,%2,%3};"
                        : "+f"(acc[mf][nf][0]), "+f"(acc[mf][nf][1]),
                          "+f"(acc[mf][nf][2]), "+f"(acc[mf][nf][3])
                        : "r"(a[mf][0]), "r"(a[mf][1]), "r"(a[mf][2]), "r"(a[mf][3]),
                          "r"(b[nf][0]), "r"(b[nf][1]));
        }
    }

    // Epilogue
    float* Cf = (float*)Cg_ + (size_t)blockIdx.z * sC;
    __nv_bfloat16* Cb = (__nv_bfloat16*)Cg_ + (size_t)blockIdx.z * sC;
    const float* Rp = RESID ? (Rg + (size_t)blockIdx.z * sC) : nullptr;
    #pragma unroll
    for (int mf = 0; mf < 2; mf++) {
        const int r0 = rowBase + mw * 32 + mf * 16 + (lane >> 2);
        #pragma unroll
        for (int nf = 0; nf < 4; nf++) {
            const int col = colBase + nw * 32 + nf * 8 + (lane & 3) * 2;
            float v0 = acc[mf][nf][0] * alpha, v1 = acc[mf][nf][1] * alpha;
            float v2 = acc[mf][nf][2] * alpha, v3 = acc[mf][nf][3] * alpha;
            if (BIAS == 2) {
                float b0 = bias[col], b1 = bias[col + 1];
                v0 += b0; v1 += b1; v2 += b0; v3 += b1;
            }
            if (BIAS == 1) {
                v0 += bias[r0]; v1 += bias[r0];
                v2 += bias[r0 + 8]; v3 += bias[r0 + 8];
            }
            if (RESID) {
                v0 += Rp[(size_t)r0 * N + col];       v1 += Rp[(size_t)r0 * N + col + 1];
                v2 += Rp[(size_t)(r0 + 8) * N + col]; v3 += Rp[(size_t)(r0 + 8) * N + col + 1];
            }
            if (OUTBF) {
                __nv_bfloat162 p0 = __floats2bfloat162_rn(v0, v1);
                __nv_bfloat162 p1 = __floats2bfloat162_rn(v2, v3);
                *(__nv_bfloat162*)(Cb + (size_t)r0 * N + col) = p0;
                *(__nv_bfloat162*)(Cb + (size_t)(r0 + 8) * N + col) = p1;
            } else {
                *(float2*)(Cf + (size_t)r0 * N + col) = make_float2(v0, v1);
                *(float2*)(Cf + (size_t)(r0 + 8) * N + col) = make_float2(v2, v3);
            }
        }
    }
}

// ---------------- Row softmax (bf16 in/out, fp32 math) -----------------------
__global__ void softmax_kernel(__nv_bfloat16* __restrict__ s) {
    __nv_bfloat162* row = (__nv_bfloat162*)(s + (size_t)blockIdx.x * NN);
    const int tid = threadIdx.x;
    float2 vals[8];
    float m = -1e30f;
    #pragma unroll
    for (int i = 0; i < 8; i++) {
        __nv_bfloat162 p = row[tid + i * 256];
        vals[i].x = __low2float(p); vals[i].y = __high2float(p);
        m = fmaxf(m, fmaxf(vals[i].x, vals[i].y));
    }
    __shared__ float red[256];
    red[tid] = m; __syncthreads();
    for (int st = 128; st > 0; st >>= 1) {
        if (tid < st) red[tid] = fmaxf(red[tid], red[tid + st]);
        __syncthreads();
    }
    m = red[0];
    __syncthreads();
    float sum = 0.f;
    #pragma unroll
    for (int i = 0; i < 8; i++) {
        vals[i].x = __expf(vals[i].x - m);
        vals[i].y = __expf(vals[i].y - m);
        sum += vals[i].x + vals[i].y;
    }
    red[tid] = sum; __syncthreads();
    for (int st = 128; st > 0; st >>= 1) {
        if (tid < st) red[tid] += red[tid + st];
        __syncthreads();
    }
    const float inv = 1.f / red[0];
    #pragma unroll
    for (int i = 0; i < 8; i++)
        row[tid + i * 256] = __floats2bfloat162_rn(vals[i].x * inv, vals[i].y * inv);
}

// ---------------- launch -----------------------------------------------------
extern "C" void kernel_launch(void* const* d_in, const int* in_sizes, int n_in,
                              void* d_out, int out_size) {
    const float* x   = (const float*)d_in[0];
    const float* gns = (const float*)d_in[1];
    const float* gnb = (const float*)d_in[2];
    const float* wq  = (const float*)d_in[3];
    const float* bq  = (const float*)d_in[4];
    const float* wk  = (const float*)d_in[5];
    const float* bk  = (const float*)d_in[6];
    const float* wv  = (const float*)d_in[7];
    const float* bv  = (const float*)d_in[8];
    const float* wp  = (const float*)d_in[9];
    const float* bp  = (const float*)d_in[10];
    float* out = (float*)d_out;

    __nv_bfloat16 *tT, *q, *k, *v, *s, *ao, *wb;
    cudaGetSymbolAddress((void**)&tT, g_tT);
    cudaGetSymbolAddress((void**)&q,  g_q);
    cudaGetSymbolAddress((void**)&k,  g_k);
    cudaGetSymbolAddress((void**)&v,  g_v);
    cudaGetSymbolAddress((void**)&s,  g_s);
    cudaGetSymbolAddress((void**)&ao, g_ao);
    cudaGetSymbolAddress((void**)&wb, g_wb);
    __nv_bfloat16 *wqb = wb, *wkb = wb + 262144, *wvb = wb + 524288, *wpb = wb + 786432;

    cudaFuncSetAttribute(mma_gemm<1,2,0>, cudaFuncAttributeMaxDynamicSharedMemorySize, SMEM_BYTES);
    cudaFuncSetAttribute(mma_gemm<1,1,0>, cudaFuncAttributeMaxDynamicSharedMemorySize, SMEM_BYTES);
    cudaFuncSetAttribute(mma_gemm<1,0,0>, cudaFuncAttributeMaxDynamicSharedMemorySize, SMEM_BYTES);
    cudaFuncSetAttribute(mma_gemm<0,1,1>, cudaFuncAttributeMaxDynamicSharedMemorySize, SMEM_BYTES);

    const size_t S  = (size_t)NN * NC;   // per-batch stride for [n][c]-like tensors
    const size_t SS = (size_t)NN * NN;   // scores stride

    // 0) weights -> bf16
    convw_kernel<<<4096, 256>>>(wq, wk, wv, wp, wb);
    // 1) GroupNorm -> tT bf16 [b][n][c]
    groupnorm_kernel<<<NB * NG, 256>>>(x, gns, gnb, tT);

    // 2) q[n][o] = tT[n][:].wq[o][:] + bq[o]
    mma_gemm<1,2,0><<<dim3(NC/128, NN/128, NB), 512, SMEM_BYTES>>>(
        tT, wqb, bq, nullptr, q, NN, NC, NC, 1.f, S, 0, S);
    // 3) k[n][o]
    mma_gemm<1,2,0><<<dim3(NC/128, NN/128, NB), 512, SMEM_BYTES>>>(
        tT, wkb, bk, nullptr, k, NN, NC, NC, 1.f, S, 0, S);
    // 4) v[o][m] = wv[o][:].tT[m][:] + bv[o]  (row bias)
    mma_gemm<1,1,0><<<dim3(NN/128, NC/128, NB), 512, SMEM_BYTES>>>(
        wvb, tT, bv, nullptr, v, NC, NN, NC, 1.f, 0, S, S);
    // 5) scores[n][m] = alpha * q[n][:].k[m][:]
    mma_gemm<1,0,0><<<dim3(NN/128, NN/128, NB), 512, SMEM_BYTES>>>(
        q, k, nullptr, nullptr, s, NN, NN, NC, 0.044194173824159216f, S, S, SS);
    // 6) softmax rows (in-place bf16)
    softmax_kernel<<<NB * NN, 256>>>(s);
    // 7) ao[n][c] = attn[n][:].v[c][:]
    mma_gemm<1,0,0><<<dim3(NC/128, NN/128, NB), 512, SMEM_BYTES>>>(
        s, v, nullptr, nullptr, ao, NN, NC, NN, 1.f, SS, S, S);
    // 8) out[o][n] = wp[o][:].ao[n][:] + bp[o] + x[o][n]
    mma_gemm<0,1,1><<<dim3(NN/128, NC/128, NB), 512, SMEM_BYTES>>>(
        wpb, ao, bp, x, out, NC, NN, NC, 1.f, 0, S, S);
}

// round 15
// speedup vs baseline: 1.1825x; 1.0792x over previous
#include <cuda_runtime.h>
#include <cuda_bf16.h>
#include <cstdint>

// Problem shape (fixed by setup_inputs)
static const int NB = 2, NC = 512, NN = 4096, NG = 32, CPG = 16;

// ---------------- scratch (allocation-free: __device__ globals) -------------
__device__ __align__(256) __nv_bfloat16 g_tT[(size_t)NB * NN * NC]; // gn(x)^T [b][n][c]
__device__ __align__(256) __nv_bfloat16 g_q [(size_t)NB * NN * NC]; // q  [b][n][o]
__device__ __align__(256) __nv_bfloat16 g_k [(size_t)NB * NN * NC]; // k  [b][n][o]
__device__ __align__(256) __nv_bfloat16 g_v [(size_t)NB * NC * NN]; // v  [b][o][m]
__device__ __align__(256) __nv_bfloat16 g_s [(size_t)NB * NN * NN]; // scores/attn [b][n][m]
__device__ __align__(256) __nv_bfloat16 g_ao[(size_t)NB * NN * NC]; // attn@v [b][n][c]
__device__ __align__(256) __nv_bfloat16 g_wb[4 * 512 * 512];        // wq,wk,wv,wp in bf16

__device__ __forceinline__ uint32_t smem_u32(const void* p) {
    uint32_t a;
    asm("{ .reg .u64 t; cvta.to.shared.u64 t, %1; cvt.u32.u64 %0, t; }"
        : "=r"(a) : "l"(p));
    return a;
}

// ---------------- weight fp32 -> bf16 ---------------------------------------
__global__ void convw_kernel(const float* __restrict__ w0, const float* __restrict__ w1,
                             const float* __restrict__ w2, const float* __restrict__ w3,
                             __nv_bfloat16* __restrict__ out) {
    int idx = blockIdx.x * 256 + threadIdx.x;           // 4*262144 total
    const float* src = (idx < 262144) ? w0 : (idx < 524288) ? w1
                     : (idx < 786432) ? w2 : w3;
    out[idx] = __float2bfloat16(src[idx & 262143]);
}

// ---------------- GroupNorm -> transposed bf16 [b][n][c] ---------------------
__global__ void groupnorm_kernel(const float* __restrict__ x,
                                 const float* __restrict__ scale,
                                 const float* __restrict__ bias,
                                 __nv_bfloat16* __restrict__ tT) {
    const int chunk = CPG * NN;                 // 65536
    const int bidx = blockIdx.x;
    const int b = bidx / NG, g = bidx % NG;
    const size_t base = (size_t)bidx * chunk;
    const int tid = threadIdx.x;

    float sum = 0.f, sumsq = 0.f;
    for (int i = tid; i < chunk; i += 256) {
        float v = x[base + i];
        sum += v; sumsq += v * v;
    }
    __shared__ float ssum[256], ssq[256];
    ssum[tid] = sum; ssq[tid] = sumsq;
    __syncthreads();
    for (int s = 128; s > 0; s >>= 1) {
        if (tid < s) { ssum[tid] += ssum[tid + s]; ssq[tid] += ssq[tid + s]; }
        __syncthreads();
    }
    const float mean = ssum[0] / (float)chunk;
    const float var  = ssq[0] / (float)chunk - mean * mean;
    const float inv  = rsqrtf(var + 1e-6f);

    const int ch0 = g * CPG;
    const int csub = (tid & 3) * 4;             // channel quad within group
    float sc[4], bi[4];
    #pragma unroll
    for (int j = 0; j < 4; j++) {
        sc[j] = scale[ch0 + csub + j] * inv;
        bi[j] = bias[ch0 + csub + j] - mean * sc[j];
    }
    for (int n = (tid >> 2); n < NN; n += 64) {
        float o0 = x[base + (size_t)(csub + 0) * NN + n] * sc[0] + bi[0];
        float o1 = x[base + (size_t)(csub + 1) * NN + n] * sc[1] + bi[1];
        float o2 = x[base + (size_t)(csub + 2) * NN + n] * sc[2] + bi[2];
        float o3 = x[base + (size_t)(csub + 3) * NN + n] * sc[3] + bi[3];
        __nv_bfloat162 p0 = __floats2bfloat162_rn(o0, o1);
        __nv_bfloat162 p1 = __floats2bfloat162_rn(o2, o3);
        uint2 u = make_uint2(*(uint32_t*)&p0, *(uint32_t*)&p1);
        *(uint2*)&tT[((size_t)b * NN + n) * NC + ch0 + csub] = u;
    }
}

// ---------------- mma.sync bf16 GEMM -----------------------------------------
// D[m][n] = alpha * sum_k A[m][k]*B[n][k] (+bias)(+resid). A,B bf16 K-major.
// Block 128x128, 4 warps (2M x 2N), warp tile 64x64, K-tile 32, 4-stage cp.async.
// Large warp tile minimizes ldmatrix replication (smem crossbar is the
// binding resource: 48KB/ktile vs 65KB at 64x32, 80KB at 32x32).
// OUTBF: 1 bf16 out, 0 fp32 out.  BIAS: 0 none, 1 row (bias[m]), 2 col (bias[n]).
static const int STG = 10240;                 // 128 rows * 80B (64B data + 16 pad)
static const int SMEM_BYTES = 8 * STG;        // A 4 stages + B 4 stages = 80KB

template <int OUTBF, int BIAS, int RESID>
__global__ void __launch_bounds__(128, 2)
mma_gemm(const __nv_bfloat16* __restrict__ Ag, const __nv_bfloat16* __restrict__ Bg,
         const float* __restrict__ bias, const float* __restrict__ Rg,
         void* __restrict__ Cg_, int M, int N, int K, float alpha,
         size_t sA, size_t sB, size_t sC) {
    extern __shared__ char smem[];
    const uint32_t sbase = smem_u32(smem);
    const uint32_t SAb = sbase, SBb = sbase + 4 * STG;

    Ag += (size_t)blockIdx.z * sA;
    Bg += (size_t)blockIdx.z * sB;

    const int tid = threadIdx.x, lane = tid & 31, wid = tid >> 5;
    const int mw = wid >> 1, nw = wid & 1;       // warp grid 2x2, warp tile 64x64
    const int rowBase = blockIdx.y * 128;
    const int colBase = blockIdx.x * 128;

    float acc[4][8][4];
    #pragma unroll
    for (int i = 0; i < 4; i++)
        #pragma unroll
        for (int j = 0; j < 8; j++)
            #pragma unroll
            for (int l = 0; l < 4; l++) acc[i][j][l] = 0.f;

    const int r_ld = tid >> 2, kb_ld = tid & 3;  // 4 chunks per thread per operand
    auto issue = [&](int st, int kt) {
        #pragma unroll
        for (int h = 0; h < 4; h++) {
            const int r = r_ld + h * 32;
            uint32_t sa0 = SAb + st * STG + r * 80 + kb_ld * 16;
            const __nv_bfloat16* ga0 = Ag + (size_t)(rowBase + r) * K + kt * 32 + kb_ld * 8;
            asm volatile("cp.async.cg.shared.global [%0], [%1], 16;" :: "r"(sa0), "l"(ga0));
            uint32_t sb0 = SBb + st * STG + r * 80 + kb_ld * 16;
            const __nv_bfloat16* gb0 = Bg + (size_t)(colBase + r) * K + kt * 32 + kb_ld * 8;
            asm volatile("cp.async.cg.shared.global [%0], [%1], 16;" :: "r"(sb0), "l"(gb0));
        }
    };

    const int ntiles = K / 32;
    issue(0, 0); asm volatile("cp.async.commit_group;" ::: "memory");
    issue(1, 1); asm volatile("cp.async.commit_group;" ::: "memory");
    issue(2, 2); asm volatile("cp.async.commit_group;" ::: "memory");

    for (int kt = 0; kt < ntiles; kt++) {
        asm volatile("cp.async.wait_group 2;" ::: "memory");
        __syncthreads();
        const int lt = kt + 3;
        if (lt < ntiles) issue(lt & 3, lt);
        asm volatile("cp.async.commit_group;" ::: "memory");

        const uint32_t ab = SAb + (kt & 3) * STG;
        const uint32_t bb = SBb + (kt & 3) * STG;
        #pragma unroll
        for (int k16 = 0; k16 < 2; k16++) {
            uint32_t a[4][4], b[8][2];
            #pragma unroll
            for (int mf = 0; mf < 4; mf++) {
                uint32_t ad = ab + (uint32_t)(mw * 64 + mf * 16 + (lane & 15)) * 80
                            + k16 * 32 + ((lane >> 4) * 16);
                asm volatile("ldmatrix.sync.aligned.m8n8.x4.shared.b16 {%0,%1,%2,%3},[%4];"
                    : "=r"(a[mf][0]), "=r"(a[mf][1]), "=r"(a[mf][2]), "=r"(a[mf][3])
                    : "r"(ad));
            }
            #pragma unroll
            for (int b2 = 0; b2 < 4; b2++) {
                const int g = lane >> 3;
                uint32_t bd = bb + (uint32_t)(nw * 64 + b2 * 16 + (g >> 1) * 8 + (lane & 7)) * 80
                            + k16 * 32 + (g & 1) * 16;
                uint32_t r0, r1, r2, r3;
                asm volatile("ldmatrix.sync.aligned.m8n8.x4.shared.b16 {%0,%1,%2,%3},[%4];"
                    : "=r"(r0), "=r"(r1), "=r"(r2), "=r"(r3) : "r"(bd));
                b[b2 * 2][0] = r0; b[b2 * 2][1] = r1;
                b[b2 * 2 + 1][0] = r2; b[b2 * 2 + 1][1] = r3;
            }
            #pragma unroll
            for (int mf = 0; mf < 4; mf++)
                #pragma unroll
                for (int nf = 0; nf < 8; nf++)
                    asm volatile(
                        "mma.sync.aligned.m16n8k16.row.col.f32.bf16.bf16.f32 "
                        "{%0,%1,%2,%3},{%4,%5,%6,%7},{%8,%9},{%0,%1,%2,%3};"
                        : "+f"(acc[mf][nf][0]), "+f"(acc[mf][nf][1]),
                          "+f"(acc[mf][nf][2]), "+f"(acc[mf][nf][3])
                        : "r"(a[mf][0]), "r"(a[mf][1]), "r"(a[mf][2]), "r"(a[mf][3]),
                          "r"(b[nf][0]), "r"(b[nf][1]));
        }
    }

    // Epilogue
    float* Cf = (float*)Cg_ + (size_t)blockIdx.z * sC;
    __nv_bfloat16* Cb = (__nv_bfloat16*)Cg_ + (size_t)blockIdx.z * sC;
    const float* Rp = RESID ? (Rg + (size_t)blockIdx.z * sC) : nullptr;
    #pragma unroll
    for (int mf = 0; mf < 4; mf++) {
        const int r0 = rowBase + mw * 64 + mf * 16 + (lane >> 2);
        #pragma unroll
        for (int nf = 0; nf < 8; nf++) {
            const int col = colBase + nw * 64 + nf * 8 + (lane & 3) * 2;
            float v0 = acc[mf][nf][0] * alpha, v1 = acc[mf][nf][1] * alpha;
            float v2 = acc[mf][nf][2] * alpha, v3 = acc[mf][nf][3] * alpha;
            if (BIAS == 2) {
                float b0 = bias[col], b1 = bias[col + 1];
                v0 += b0; v1 += b1; v2 += b0; v3 += b1;
            }
            if (BIAS == 1) {
                v0 += bias[r0]; v1 += bias[r0];
                v2 += bias[r0 + 8]; v3 += bias[r0 + 8];
            }
            if (RESID) {
                v0 += Rp[(size_t)r0 * N + col];       v1 += Rp[(size_t)r0 * N + col + 1];
                v2 += Rp[(size_t)(r0 + 8) * N + col]; v3 += Rp[(size_t)(r0 + 8) * N + col + 1];
            }
            if (OUTBF) {
                __nv_bfloat162 p0 = __floats2bfloat162_rn(v0, v1);
                __nv_bfloat162 p1 = __floats2bfloat162_rn(v2, v3);
                *(__nv_bfloat162*)(Cb + (size_t)r0 * N + col) = p0;
                *(__nv_bfloat162*)(Cb + (size_t)(r0 + 8) * N + col) = p1;
            } else {
                *(float2*)(Cf + (size_t)r0 * N + col) = make_float2(v0, v1);
                *(float2*)(Cf + (size_t)(r0 + 8) * N + col) = make_float2(v2, v3);
            }
        }
    }
}

// ---------------- Row softmax (bf16 in/out, fp32 math) -----------------------
__global__ void softmax_kernel(__nv_bfloat16* __restrict__ s) {
    __nv_bfloat162* row = (__nv_bfloat162*)(s + (size_t)blockIdx.x * NN);
    const int tid = threadIdx.x;
    float2 vals[8];
    float m = -1e30f;
    #pragma unroll
    for (int i = 0; i < 8; i++) {
        __nv_bfloat162 p = row[tid + i * 256];
        vals[i].x = __low2float(p); vals[i].y = __high2float(p);
        m = fmaxf(m, fmaxf(vals[i].x, vals[i].y));
    }
    __shared__ float red[256];
    red[tid] = m; __syncthreads();
    for (int st = 128; st > 0; st >>= 1) {
        if (tid < st) red[tid] = fmaxf(red[tid], red[tid + st]);
        __syncthreads();
    }
    m = red[0];
    __syncthreads();
    float sum = 0.f;
    #pragma unroll
    for (int i = 0; i < 8; i++) {
        vals[i].x = __expf(vals[i].x - m);
        vals[i].y = __expf(vals[i].y - m);
        sum += vals[i].x + vals[i].y;
    }
    red[tid] = sum; __syncthreads();
    for (int st = 128; st > 0; st >>= 1) {
        if (tid < st) red[tid] += red[tid + st];
        __syncthreads();
    }
    const float inv = 1.f / red[0];
    #pragma unroll
    for (int i = 0; i < 8; i++)
        row[tid + i * 256] = __floats2bfloat162_rn(vals[i].x * inv, vals[i].y * inv);
}

// ---------------- launch -----------------------------------------------------
extern "C" void kernel_launch(void* const* d_in, const int* in_sizes, int n_in,
                              void* d_out, int out_size) {
    const float* x   = (const float*)d_in[0];
    const float* gns = (const float*)d_in[1];
    const float* gnb = (const float*)d_in[2];
    const float* wq  = (const float*)d_in[3];
    const float* bq  = (const float*)d_in[4];
    const float* wk  = (const float*)d_in[5];
    const float* bk  = (const float*)d_in[6];
    const float* wv  = (const float*)d_in[7];
    const float* bv  = (const float*)d_in[8];
    const float* wp  = (const float*)d_in[9];
    const float* bp  = (const float*)d_in[10];
    float* out = (float*)d_out;

    __nv_bfloat16 *tT, *q, *k, *v, *s, *ao, *wb;
    cudaGetSymbolAddress((void**)&tT, g_tT);
    cudaGetSymbolAddress((void**)&q,  g_q);
    cudaGetSymbolAddress((void**)&k,  g_k);
    cudaGetSymbolAddress((void**)&v,  g_v);
    cudaGetSymbolAddress((void**)&s,  g_s);
    cudaGetSymbolAddress((void**)&ao, g_ao);
    cudaGetSymbolAddress((void**)&wb, g_wb);
    __nv_bfloat16 *wqb = wb, *wkb = wb + 262144, *wvb = wb + 524288, *wpb = wb + 786432;

    cudaFuncSetAttribute(mma_gemm<1,2,0>, cudaFuncAttributeMaxDynamicSharedMemorySize, SMEM_BYTES);
    cudaFuncSetAttribute(mma_gemm<1,1,0>, cudaFuncAttributeMaxDynamicSharedMemorySize, SMEM_BYTES);
    cudaFuncSetAttribute(mma_gemm<1,0,0>, cudaFuncAttributeMaxDynamicSharedMemorySize, SMEM_BYTES);
    cudaFuncSetAttribute(mma_gemm<0,1,1>, cudaFuncAttributeMaxDynamicSharedMemorySize, SMEM_BYTES);

    const size_t S  = (size_t)NN * NC;   // per-batch stride for [n][c]-like tensors
    const size_t SS = (size_t)NN * NN;   // scores stride

    // 0) weights -> bf16
    convw_kernel<<<4096, 256>>>(wq, wk, wv, wp, wb);
    // 1) GroupNorm -> tT bf16 [b][n][c]
    groupnorm_kernel<<<NB * NG, 256>>>(x, gns, gnb, tT);

    // 2) q[n][o] = tT[n][:].wq[o][:] + bq[o]
    mma_gemm<1,2,0><<<dim3(NC/128, NN/128, NB), 128, SMEM_BYTES>>>(
        tT, wqb, bq, nullptr, q, NN, NC, NC, 1.f, S, 0, S);
    // 3) k[n][o]
    mma_gemm<1,2,0><<<dim3(NC/128, NN/128, NB), 128, SMEM_BYTES>>>(
        tT, wkb, bk, nullptr, k, NN, NC, NC, 1.f, S, 0, S);
    // 4) v[o][m] = wv[o][:].tT[m][:] + bv[o]  (row bias)
    mma_gemm<1,1,0><<<dim3(NN/128, NC/128, NB), 128, SMEM_BYTES>>>(
        wvb, tT, bv, nullptr, v, NC, NN, NC, 1.f, 0, S, S);
    // 5) scores[n][m] = alpha * q[n][:].k[m][:]
    mma_gemm<1,0,0><<<dim3(NN/128, NN/128, NB), 128, SMEM_BYTES>>>(
        q, k, nullptr, nullptr, s, NN, NN, NC, 0.044194173824159216f, S, S, SS);
    // 6) softmax rows (in-place bf16)
    softmax_kernel<<<NB * NN, 256>>>(s);
    // 7) ao[n][c] = attn[n][:].v[c][:]
    mma_gemm<1,0,0><<<dim3(NC/128, NN/128, NB), 128, SMEM_BYTES>>>(
        s, v, nullptr, nullptr, ao, NN, NC, NN, 1.f, SS, S, S);
    // 8) out[o][n] = wp[o][:].ao[n][:] + bp[o] + x[o][n]
    mma_gemm<0,1,1><<<dim3(NN/128, NC/128, NB), 128, SMEM_BYTES>>>(
        wpb, ao, bp, x, out, NC, NN, NC, 1.f, 0, S, S);
}